// round 3
// baseline (speedup 1.0000x reference)
#include <cuda_runtime.h>
#include <cstdint>
#include <cstddef>

#define N_PTS 8192
#define DD    256
#define BATCH 8
#define S_MAX 2048

// Scratch (static device globals — allocation-free per harness rules)
__device__ int   g_idx[BATCH * S_MAX];          // FPS indices (prefix-shared across scales)
__device__ float g_h[28672 * 256];              // layer-1 / fusion-layer-1 outputs
__device__ float g_proc[28672 * 256];           // proc0 | proc1 | proc2 (rows 0,4096,12288)

// ---- packed f32x2 helpers (per-lane IEEE rn — bit-identical to scalar ops) ----
__device__ __forceinline__ unsigned long long pk2(float lo, float hi) {
    unsigned long long r;
    asm("mov.b64 %0, {%1, %2};" : "=l"(r) : "f"(lo), "f"(hi));
    return r;
}
__device__ __forceinline__ void upk2(unsigned long long v, float& lo, float& hi) {
    asm("mov.b64 {%0, %1}, %2;" : "=f"(lo), "=f"(hi) : "l"(v));
}
__device__ __forceinline__ unsigned long long add2(unsigned long long a, unsigned long long b) {
    unsigned long long r;
    asm("add.rn.f32x2 %0, %1, %2;" : "=l"(r) : "l"(a), "l"(b));
    return r;
}
__device__ __forceinline__ unsigned long long mul2(unsigned long long a, unsigned long long b) {
    unsigned long long r;
    asm("mul.rn.f32x2 %0, %1, %2;" : "=l"(r) : "l"(a), "l"(b));
    return r;
}

// ---------------------------------------------------------------------------
// FPS: one CTA per batch, 1024 threads, 8 points/thread in registers.
// ONE __syncthreads per step: double-buffered s_warp by step parity; all warps
// redundantly butterfly-reduce the 32 warp keys so no warp serializes/waits.
// Rounding order bit-matches JAX: ((dx*dx + dy*dy) + dz*dz), all rn, no FMA.
// First-index tie-break via packed u64 key (dist_bits, 8191-idx).
// ---------------------------------------------------------------------------
__global__ void __launch_bounds__(1024, 1)
fps_kernel(const float* __restrict__ xyz, int* __restrict__ outIdx)
{
    const int b = blockIdx.x;
    const float* p = xyz + (size_t)b * N_PTS * 3;
    const int t = threadIdx.x;
    const int lane = t & 31, wid = t >> 5;
    const int base = t * 8;

    unsigned long long px2[4], py2[4], pz2[4];
    float dist[8];
#pragma unroll
    for (int j = 0; j < 4; j++) {
        const int k0 = base + 2 * j, k1 = k0 + 1;
        px2[j] = pk2(p[k0 * 3 + 0], p[k1 * 3 + 0]);
        py2[j] = pk2(p[k0 * 3 + 1], p[k1 * 3 + 1]);
        pz2[j] = pk2(p[k0 * 3 + 2], p[k1 * 3 + 2]);
    }
#pragma unroll
    for (int k = 0; k < 8; k++) dist[k] = 1e10f;

    __shared__ unsigned long long s_warp[2][32];

    float qx = p[0], qy = p[1], qz = p[2];
    if (t == 0) outIdx[b * S_MAX + 0] = 0;

    for (int step = 1; step < S_MAX; step++) {
        const unsigned long long nqx = pk2(-qx, -qx);
        const unsigned long long nqy = pk2(-qy, -qy);
        const unsigned long long nqz = pk2(-qz, -qz);

        float best = -1.0f;
        int bidx = 0;
#pragma unroll
        for (int j = 0; j < 4; j++) {
            unsigned long long dx = add2(px2[j], nqx);
            unsigned long long dy = add2(py2[j], nqy);
            unsigned long long dz = add2(pz2[j], nqz);
            unsigned long long s  = add2(mul2(dx, dx), mul2(dy, dy));
            unsigned long long d2 = add2(s, mul2(dz, dz));
            float d0, d1;
            upk2(d2, d0, d1);
            float nd0 = fminf(dist[2 * j + 0], d0);
            float nd1 = fminf(dist[2 * j + 1], d1);
            dist[2 * j + 0] = nd0;
            dist[2 * j + 1] = nd1;
            if (nd0 > best) { best = nd0; bidx = base + 2 * j + 0; }
            if (nd1 > best) { best = nd1; bidx = base + 2 * j + 1; }
        }
        unsigned long long key =
            ((unsigned long long)__float_as_uint(best) << 32) |
            (unsigned)(8191 - bidx);
        // warp butterfly max (all lanes end with warp max)
#pragma unroll
        for (int o = 16; o > 0; o >>= 1) {
            unsigned long long other = __shfl_xor_sync(0xFFFFFFFFu, key, o);
            if (other > key) key = other;
        }
        const int buf = step & 1;
        if (lane == 0) s_warp[buf][wid] = key;
        __syncthreads();
        // every warp redundantly reduces the 32 warp keys (no second barrier;
        // parity double-buffer prevents write-after-read races across steps)
        unsigned long long k2 = s_warp[buf][lane];
#pragma unroll
        for (int o = 16; o > 0; o >>= 1) {
            unsigned long long other = __shfl_xor_sync(0xFFFFFFFFu, k2, o);
            if (other > k2) k2 = other;
        }
        const int widx = 8191 - (int)(k2 & 0xFFFFFFFFu);
        if (t == 0) outIdx[b * S_MAX + step] = widx;
        qx = p[widx * 3 + 0];
        qy = p[widx * 3 + 1];
        qz = p[widx * 3 + 2];
    }
}

// ---------------------------------------------------------------------------
// Fused fp32 GEMM: C[M,256] = A[M,K] @ B[K,256] (+bias) (+LayerNorm+ReLU)
//   AMODE 0: MULTI-SCALE layer-1: block ranges cover all 3 scales in ONE grid;
//            A rows gathered via FPS idx from features [B,8192,256]
//   AMODE 1: A rows read directly (A + r*256)
//   AMODE 2: A rows are the virtual concat [proc0 | proc1 | proc2] (K=768)
//   AMODE 3: MULTI-SCALE layer-2: direct rows at per-scale offsets
//   EMODE 0: +bias, store
//   EMODE 1: +bias, LayerNorm(gamma,beta), ReLU, store
//   EMODE 2: +bias, store 4 tiled copies (n = m + k*2048) into [B,8192,256]
// Tile: BM=32, BN=256, BK=16, 256 threads, 4x8 microtile, double-buffered smem.
// Multi-scale block map (32-row blocks): [0,128)->s=512 rowoff=0,
//   [128,384)->s=1024 rowoff=4096, [384,896)->s=2048 rowoff=12288.
// ---------------------------------------------------------------------------
template <int AMODE, int EMODE>
__global__ void __launch_bounds__(256, 3)
gemm_fused(const float* __restrict__ A, const float* __restrict__ Bm,
           const float* __restrict__ bias, const float* __restrict__ gamma,
           const float* __restrict__ beta, float* __restrict__ C,
           int K, const int* __restrict__ idx)
{
    __shared__ float As[2][32][16];
    __shared__ float Bs[2][16][256];

    const int tid  = threadIdx.x;
    const int lane = tid & 31, warp = tid >> 5;

    int rowblock, sc = 0, rowoff = 0, sloc = 0;
    if (AMODE == 0 || AMODE == 3) {
        const int blk = blockIdx.x;
        if (blk < 128)      { sc = 0; rowblock = blk * 32;         sloc = 512;  rowoff = 0; }
        else if (blk < 384) { sc = 1; rowblock = (blk - 128) * 32; sloc = 1024; rowoff = 4096; }
        else                { sc = 2; rowblock = (blk - 384) * 32; sloc = 2048; rowoff = 12288; }
    } else {
        rowblock = blockIdx.x * 32;
    }
    const float* Bmp   = Bm + (size_t)sc * 65536;
    const float* biasp = bias + sc * 256;

    // ---- A-load mapping (threads 0..127 load one float4 per k-tile) ----
    const int arow = tid >> 2;            // 0..63 (only <32 used when tid<128)
    const int akq  = (tid & 3) << 2;      // {0,4,8,12}
    const int r    = rowblock + (arow & 31);
    const float* aptr0 = A;
    const float* aptr1 = A;
    const float* aptr2 = A;
    if (AMODE == 0) {
        int bb = r / sloc, j = r - bb * sloc;
        int src = idx[bb * 2048 + j];
        aptr0 = A + ((size_t)bb * 8192 + src) * 256;
    } else if (AMODE == 1) {
        aptr0 = A + (size_t)r * 256;
    } else if (AMODE == 3) {
        aptr0 = A + (size_t)(rowoff + r) * 256;
    } else {
        int bb = r >> 11, m = r & 2047;
        aptr0 = A +            ((size_t)bb * 512  + (m & 511))  * 256;
        aptr1 = A + 1048576 +  ((size_t)bb * 1024 + (m & 1023)) * 256;
        aptr2 = A + 3145728 +  ((size_t)bb * 2048 + m)          * 256;
    }
    const bool aload = (tid < 128);

    // ---- B-load mapping (4 float4 per thread per k-tile) ----
    const int brow = tid >> 6;            // 0..3
    const int bcol = (tid & 63) << 2;     // 0..252

    float acc[4][8];
#pragma unroll
    for (int i = 0; i < 4; i++)
#pragma unroll
        for (int j = 0; j < 8; j++) acc[i][j] = 0.f;

    const int ktiles = K >> 4;
    float4 ra;
    float4 rb[4];

    // prologue: load tile 0
    if (aload) ra = *reinterpret_cast<const float4*>(aptr0 + akq);
#pragma unroll
    for (int i = 0; i < 4; i++)
        rb[i] = *reinterpret_cast<const float4*>(Bmp + (size_t)(brow + 4 * i) * 256 + bcol);
    if (aload) *reinterpret_cast<float4*>(&As[0][arow][akq]) = ra;
#pragma unroll
    for (int i = 0; i < 4; i++)
        *reinterpret_cast<float4*>(&Bs[0][brow + 4 * i][bcol]) = rb[i];
    __syncthreads();

    for (int kt = 0; kt < ktiles; kt++) {
        const int cur = kt & 1;
        if (kt + 1 < ktiles) {
            const int k0 = (kt + 1) << 4;
            if (aload) {
                if (AMODE == 2) {
                    int seg = k0 >> 8;
                    int kk  = (k0 & 255) + akq;
                    const float* bp = (seg == 0) ? aptr0 : ((seg == 1) ? aptr1 : aptr2);
                    ra = *reinterpret_cast<const float4*>(bp + kk);
                } else {
                    ra = *reinterpret_cast<const float4*>(aptr0 + k0 + akq);
                }
            }
#pragma unroll
            for (int i = 0; i < 4; i++)
                rb[i] = *reinterpret_cast<const float4*>(Bmp + (size_t)(k0 + brow + 4 * i) * 256 + bcol);
        }
#pragma unroll
        for (int kk = 0; kk < 16; kk++) {
            float a[4];
#pragma unroll
            for (int ii = 0; ii < 4; ii++) a[ii] = As[cur][warp * 4 + ii][kk];
            float4 b0 = *reinterpret_cast<const float4*>(&Bs[cur][kk][lane * 4]);
            float4 b1 = *reinterpret_cast<const float4*>(&Bs[cur][kk][128 + lane * 4]);
            float bv[8] = {b0.x, b0.y, b0.z, b0.w, b1.x, b1.y, b1.z, b1.w};
#pragma unroll
            for (int ii = 0; ii < 4; ii++)
#pragma unroll
                for (int jj = 0; jj < 8; jj++)
                    acc[ii][jj] = fmaf(a[ii], bv[jj], acc[ii][jj]);
        }
        if (kt + 1 < ktiles) {
            const int nb = cur ^ 1;
            if (aload) *reinterpret_cast<float4*>(&As[nb][arow][akq]) = ra;
#pragma unroll
            for (int i = 0; i < 4; i++)
                *reinterpret_cast<float4*>(&Bs[nb][brow + 4 * i][bcol]) = rb[i];
        }
        __syncthreads();
    }

    // ---- epilogue ----
    const int c0 = lane * 4, c1 = 128 + lane * 4;
    {
        float4 t0 = *reinterpret_cast<const float4*>(biasp + c0);
        float4 t1 = *reinterpret_cast<const float4*>(biasp + c1);
        float bsv[8] = {t0.x, t0.y, t0.z, t0.w, t1.x, t1.y, t1.z, t1.w};
#pragma unroll
        for (int ii = 0; ii < 4; ii++)
#pragma unroll
            for (int jj = 0; jj < 8; jj++) acc[ii][jj] += bsv[jj];
    }

    float gv[8], ev[8];
    if (EMODE == 1) {
        const float* gp = gamma + sc * 256;
        const float* bp = beta + sc * 256;
        float4 t0 = *reinterpret_cast<const float4*>(gp + c0);
        float4 t1 = *reinterpret_cast<const float4*>(gp + c1);
        gv[0]=t0.x; gv[1]=t0.y; gv[2]=t0.z; gv[3]=t0.w;
        gv[4]=t1.x; gv[5]=t1.y; gv[6]=t1.z; gv[7]=t1.w;
        float4 u0 = *reinterpret_cast<const float4*>(bp + c0);
        float4 u1 = *reinterpret_cast<const float4*>(bp + c1);
        ev[0]=u0.x; ev[1]=u0.y; ev[2]=u0.z; ev[3]=u0.w;
        ev[4]=u1.x; ev[5]=u1.y; ev[6]=u1.z; ev[7]=u1.w;
    }

#pragma unroll
    for (int ii = 0; ii < 4; ii++) {
        const int row = rowoff + rowblock + warp * 4 + ii;
        float o8[8];
        if (EMODE == 1) {
            float sum = 0.f;
#pragma unroll
            for (int jj = 0; jj < 8; jj++) sum += acc[ii][jj];
#pragma unroll
            for (int o = 16; o > 0; o >>= 1) sum += __shfl_xor_sync(0xFFFFFFFFu, sum, o);
            const float mu = sum * (1.0f / 256.0f);
            float sq = 0.f;
#pragma unroll
            for (int jj = 0; jj < 8; jj++) {
                float dd = acc[ii][jj] - mu;
                sq += dd * dd;
            }
#pragma unroll
            for (int o = 16; o > 0; o >>= 1) sq += __shfl_xor_sync(0xFFFFFFFFu, sq, o);
            const float sc2 = rsqrtf(sq * (1.0f / 256.0f) + 1e-5f);
#pragma unroll
            for (int jj = 0; jj < 8; jj++) {
                float v = fmaf((acc[ii][jj] - mu) * sc2, gv[jj], ev[jj]);
                o8[jj] = fmaxf(v, 0.f);
            }
        } else {
#pragma unroll
            for (int jj = 0; jj < 8; jj++) o8[jj] = acc[ii][jj];
        }
        float4 s0 = make_float4(o8[0], o8[1], o8[2], o8[3]);
        float4 s1 = make_float4(o8[4], o8[5], o8[6], o8[7]);
        if (EMODE == 2) {
            const int bb2 = row >> 11, m = row & 2047;
            const size_t base0 = ((size_t)bb2 * 8192 + m) * 256;
#pragma unroll
            for (int rep = 0; rep < 4; rep++) {
                *reinterpret_cast<float4*>(C + base0 + (size_t)rep * 524288 + c0) = s0;
                *reinterpret_cast<float4*>(C + base0 + (size_t)rep * 524288 + c1) = s1;
            }
        } else {
            *reinterpret_cast<float4*>(C + (size_t)row * 256 + c0) = s0;
            *reinterpret_cast<float4*>(C + (size_t)row * 256 + c1) = s1;
        }
    }
}

// ---------------------------------------------------------------------------
extern "C" void kernel_launch(void* const* d_in, const int* in_sizes, int n_in,
                              void* d_out, int out_size)
{
    const float* features = (const float*)d_in[0];
    const float* xyz      = (const float*)d_in[1];
    const float* w1  = (const float*)d_in[2];
    const float* b1  = (const float*)d_in[3];
    const float* g1  = (const float*)d_in[4];
    const float* be1 = (const float*)d_in[5];
    const float* w2  = (const float*)d_in[6];
    const float* b2  = (const float*)d_in[7];
    const float* fw1 = (const float*)d_in[8];
    const float* fb1 = (const float*)d_in[9];
    const float* fg  = (const float*)d_in[10];
    const float* fbe = (const float*)d_in[11];
    const float* fw2 = (const float*)d_in[12];
    const float* fb2 = (const float*)d_in[13];
    float* out = (float*)d_out;

    int*   idxp;
    float* hp;
    float* procp;
    cudaGetSymbolAddress((void**)&idxp, g_idx);
    cudaGetSymbolAddress((void**)&hp, g_h);
    cudaGetSymbolAddress((void**)&procp, g_proc);

    // 1) One FPS run per batch for the largest scale; smaller scales are prefixes.
    fps_kernel<<<BATCH, 1024>>>(xyz, idxp);

    // 2) All 3 per-scale MLPs, each layer as ONE 896-CTA launch.
    gemm_fused<0, 1><<<896, 256>>>(features, w1, b1, g1, be1, hp, 256, idxp);
    gemm_fused<3, 0><<<896, 256>>>(hp, w2, b2, nullptr, nullptr, procp, 256, nullptr);

    // 3) Fusion MLP on only B*2048 distinct rows (output depends on n mod 2048),
    //    final GEMM epilogue writes each row 4x to rebuild [B, 8192, D].
    gemm_fused<2, 1><<<512, 256>>>(procp, fw1, fb1, fg, fbe, hp, 768, nullptr);
    gemm_fused<1, 2><<<512, 256>>>(hp, fw2, fb2, nullptr, nullptr, out, 256, nullptr);
}

// round 4
// speedup vs baseline: 1.2277x; 1.2277x over previous
#include <cuda_runtime.h>
#include <cstdint>
#include <cstddef>

#define N_PTS 8192
#define DD    256
#define BATCH 8
#define S_MAX 2048

// Scratch (static device globals — allocation-free per harness rules)
__device__ int   g_idx[BATCH * S_MAX];          // FPS indices (prefix-shared across scales)
__device__ float g_h[28672 * 256];              // layer-1 / fusion-layer-1 outputs
__device__ float g_proc[28672 * 256];           // proc0 | proc1 | proc2 (rows 0,4096,12288)

// ---- packed f32x2 helpers (per-lane IEEE rn — bit-identical to scalar ops) ----
__device__ __forceinline__ unsigned long long pk2(float lo, float hi) {
    unsigned long long r;
    asm("mov.b64 %0, {%1, %2};" : "=l"(r) : "f"(lo), "f"(hi));
    return r;
}
__device__ __forceinline__ void upk2(unsigned long long v, float& lo, float& hi) {
    asm("mov.b64 {%0, %1}, %2;" : "=f"(lo), "=f"(hi) : "l"(v));
}
__device__ __forceinline__ unsigned long long add2(unsigned long long a, unsigned long long b) {
    unsigned long long r;
    asm("add.rn.f32x2 %0, %1, %2;" : "=l"(r) : "l"(a), "l"(b));
    return r;
}
__device__ __forceinline__ unsigned long long mul2(unsigned long long a, unsigned long long b) {
    unsigned long long r;
    asm("mul.rn.f32x2 %0, %1, %2;" : "=l"(r) : "l"(a), "l"(b));
    return r;
}

// ---------------------------------------------------------------------------
// FPS: one CTA per batch, 1024 threads, 8 points/thread in registers.
// Argmax via REDUX.MAX on float-as-uint (exact: dists >= 0 so unsigned order
// == float order) + ballot/ffs index recovery (exact first-index tie-break:
// lowest lane / lowest warp == lowest point index).
// ONE __syncthreads per step (parity double-buffered smem).
// Rounding order bit-matches JAX: ((dx*dx + dy*dy) + dz*dz), all rn, no FMA.
// ---------------------------------------------------------------------------
__global__ void __launch_bounds__(1024, 1)
fps_kernel(const float* __restrict__ xyz, int* __restrict__ outIdx)
{
    const int b = blockIdx.x;
    const float* p = xyz + (size_t)b * N_PTS * 3;
    const int t = threadIdx.x;
    const int lane = t & 31, wid = t >> 5;
    const int base = t * 8;

    unsigned long long px2[4], py2[4], pz2[4];
    float dist[8];
#pragma unroll
    for (int j = 0; j < 4; j++) {
        const int k0 = base + 2 * j, k1 = k0 + 1;
        px2[j] = pk2(p[k0 * 3 + 0], p[k1 * 3 + 0]);
        py2[j] = pk2(p[k0 * 3 + 1], p[k1 * 3 + 1]);
        pz2[j] = pk2(p[k0 * 3 + 2], p[k1 * 3 + 2]);
    }
#pragma unroll
    for (int k = 0; k < 8; k++) dist[k] = 1e10f;

    __shared__ unsigned s_val[2][32];
    __shared__ int      s_idx[2][32];

    float qx = p[0], qy = p[1], qz = p[2];
    if (t == 0) outIdx[b * S_MAX + 0] = 0;

    for (int step = 1; step < S_MAX; step++) {
        const unsigned long long nqx = pk2(-qx, -qx);
        const unsigned long long nqy = pk2(-qy, -qy);
        const unsigned long long nqz = pk2(-qz, -qz);

        float best = -1.0f;
        int bidx = 0;
#pragma unroll
        for (int j = 0; j < 4; j++) {
            unsigned long long dx = add2(px2[j], nqx);
            unsigned long long dy = add2(py2[j], nqy);
            unsigned long long dz = add2(pz2[j], nqz);
            unsigned long long s  = add2(mul2(dx, dx), mul2(dy, dy));
            unsigned long long d2 = add2(s, mul2(dz, dz));
            float d0, d1;
            upk2(d2, d0, d1);
            float nd0 = fminf(dist[2 * j + 0], d0);
            float nd1 = fminf(dist[2 * j + 1], d1);
            dist[2 * j + 0] = nd0;
            dist[2 * j + 1] = nd1;
            if (nd0 > best) { best = nd0; bidx = base + 2 * j + 0; }
            if (nd1 > best) { best = nd1; bidx = base + 2 * j + 1; }
        }

        // ---- warp stage: REDUX.MAX on f32 bits (all dists >= 0) ----
        const unsigned bestbits = __float_as_uint(best);
        const unsigned wmax = __reduce_max_sync(0xFFFFFFFFu, bestbits);
        const unsigned bal  = __ballot_sync(0xFFFFFFFFu, bestbits == wmax);
        const int srcl = __ffs(bal) - 1;                   // lowest lane = lowest idx
        const int widx_w = __shfl_sync(0xFFFFFFFFu, bidx, srcl);

        const int buf = step & 1;
        if (lane == 0) { s_val[buf][wid] = wmax; s_idx[buf][wid] = widx_w; }
        __syncthreads();

        // ---- cross-warp stage (every warp redundantly; no 2nd barrier) ----
        const unsigned v = s_val[buf][lane];
        const unsigned bmax = __reduce_max_sync(0xFFFFFFFFu, v);
        const unsigned bal2 = __ballot_sync(0xFFFFFFFFu, v == bmax);
        const int wsrc = __ffs(bal2) - 1;                  // lowest warp = lowest idx
        const int widx = s_idx[buf][wsrc];

        if (t == 0) outIdx[b * S_MAX + step] = widx;
        qx = p[widx * 3 + 0];
        qy = p[widx * 3 + 1];
        qz = p[widx * 3 + 2];
    }
}

// ---------------------------------------------------------------------------
// Fused fp32 GEMM: C[M,256] = A[M,K] @ B[K,256] (+bias) (+LayerNorm+ReLU)
//   AMODE 0: MULTI-SCALE layer-1: block ranges cover all 3 scales in ONE grid;
//            A rows gathered via FPS idx from features [B,8192,256]
//   AMODE 1: A rows read directly (A + r*256)
//   AMODE 2: A rows are the virtual concat [proc0 | proc1 | proc2] (K=768)
//   AMODE 3: MULTI-SCALE layer-2: direct rows at per-scale offsets
//   EMODE 0: +bias, store
//   EMODE 1: +bias, LayerNorm(gamma,beta), ReLU, store
//   EMODE 2: +bias, store 4 tiled copies (n = m + k*2048) into [B,8192,256]
// Tile: BM=32, BN=256, BK=16, 256 threads, 4x8 microtile, double-buffered smem.
// Multi-scale block map (32-row blocks): [0,128)->s=512 rowoff=0,
//   [128,384)->s=1024 rowoff=4096, [384,896)->s=2048 rowoff=12288.
// ---------------------------------------------------------------------------
template <int AMODE, int EMODE>
__global__ void __launch_bounds__(256, 3)
gemm_fused(const float* __restrict__ A, const float* __restrict__ Bm,
           const float* __restrict__ bias, const float* __restrict__ gamma,
           const float* __restrict__ beta, float* __restrict__ C,
           int K, const int* __restrict__ idx)
{
    __shared__ float As[2][32][16];
    __shared__ float Bs[2][16][256];

    const int tid  = threadIdx.x;
    const int lane = tid & 31, warp = tid >> 5;

    int rowblock, sc = 0, rowoff = 0, sloc = 0;
    if (AMODE == 0 || AMODE == 3) {
        const int blk = blockIdx.x;
        if (blk < 128)      { sc = 0; rowblock = blk * 32;         sloc = 512;  rowoff = 0; }
        else if (blk < 384) { sc = 1; rowblock = (blk - 128) * 32; sloc = 1024; rowoff = 4096; }
        else                { sc = 2; rowblock = (blk - 384) * 32; sloc = 2048; rowoff = 12288; }
    } else {
        rowblock = blockIdx.x * 32;
    }
    const float* Bmp   = Bm + (size_t)sc * 65536;
    const float* biasp = bias + sc * 256;

    // ---- A-load mapping (threads 0..127 load one float4 per k-tile) ----
    const int arow = tid >> 2;            // 0..63 (only <32 used when tid<128)
    const int akq  = (tid & 3) << 2;      // {0,4,8,12}
    const int r    = rowblock + (arow & 31);
    const float* aptr0 = A;
    const float* aptr1 = A;
    const float* aptr2 = A;
    if (AMODE == 0) {
        int bb = r / sloc, j = r - bb * sloc;
        int src = idx[bb * 2048 + j];
        aptr0 = A + ((size_t)bb * 8192 + src) * 256;
    } else if (AMODE == 1) {
        aptr0 = A + (size_t)r * 256;
    } else if (AMODE == 3) {
        aptr0 = A + (size_t)(rowoff + r) * 256;
    } else {
        int bb = r >> 11, m = r & 2047;
        aptr0 = A +            ((size_t)bb * 512  + (m & 511))  * 256;
        aptr1 = A + 1048576 +  ((size_t)bb * 1024 + (m & 1023)) * 256;
        aptr2 = A + 3145728 +  ((size_t)bb * 2048 + m)          * 256;
    }
    const bool aload = (tid < 128);

    // ---- B-load mapping (4 float4 per thread per k-tile) ----
    const int brow = tid >> 6;            // 0..3
    const int bcol = (tid & 63) << 2;     // 0..252

    float acc[4][8];
#pragma unroll
    for (int i = 0; i < 4; i++)
#pragma unroll
        for (int j = 0; j < 8; j++) acc[i][j] = 0.f;

    const int ktiles = K >> 4;
    float4 ra;
    float4 rb[4];

    // prologue: load tile 0
    if (aload) ra = *reinterpret_cast<const float4*>(aptr0 + akq);
#pragma unroll
    for (int i = 0; i < 4; i++)
        rb[i] = *reinterpret_cast<const float4*>(Bmp + (size_t)(brow + 4 * i) * 256 + bcol);
    if (aload) *reinterpret_cast<float4*>(&As[0][arow][akq]) = ra;
#pragma unroll
    for (int i = 0; i < 4; i++)
        *reinterpret_cast<float4*>(&Bs[0][brow + 4 * i][bcol]) = rb[i];
    __syncthreads();

    for (int kt = 0; kt < ktiles; kt++) {
        const int cur = kt & 1;
        if (kt + 1 < ktiles) {
            const int k0 = (kt + 1) << 4;
            if (aload) {
                if (AMODE == 2) {
                    int seg = k0 >> 8;
                    int kk  = (k0 & 255) + akq;
                    const float* bp = (seg == 0) ? aptr0 : ((seg == 1) ? aptr1 : aptr2);
                    ra = *reinterpret_cast<const float4*>(bp + kk);
                } else {
                    ra = *reinterpret_cast<const float4*>(aptr0 + k0 + akq);
                }
            }
#pragma unroll
            for (int i = 0; i < 4; i++)
                rb[i] = *reinterpret_cast<const float4*>(Bmp + (size_t)(k0 + brow + 4 * i) * 256 + bcol);
        }
#pragma unroll
        for (int kk = 0; kk < 16; kk++) {
            float a[4];
#pragma unroll
            for (int ii = 0; ii < 4; ii++) a[ii] = As[cur][warp * 4 + ii][kk];
            float4 b0 = *reinterpret_cast<const float4*>(&Bs[cur][kk][lane * 4]);
            float4 b1 = *reinterpret_cast<const float4*>(&Bs[cur][kk][128 + lane * 4]);
            float bv[8] = {b0.x, b0.y, b0.z, b0.w, b1.x, b1.y, b1.z, b1.w};
#pragma unroll
            for (int ii = 0; ii < 4; ii++)
#pragma unroll
                for (int jj = 0; jj < 8; jj++)
                    acc[ii][jj] = fmaf(a[ii], bv[jj], acc[ii][jj]);
        }
        if (kt + 1 < ktiles) {
            const int nb = cur ^ 1;
            if (aload) *reinterpret_cast<float4*>(&As[nb][arow][akq]) = ra;
#pragma unroll
            for (int i = 0; i < 4; i++)
                *reinterpret_cast<float4*>(&Bs[nb][brow + 4 * i][bcol]) = rb[i];
        }
        __syncthreads();
    }

    // ---- epilogue ----
    const int c0 = lane * 4, c1 = 128 + lane * 4;
    {
        float4 t0 = *reinterpret_cast<const float4*>(biasp + c0);
        float4 t1 = *reinterpret_cast<const float4*>(biasp + c1);
        float bsv[8] = {t0.x, t0.y, t0.z, t0.w, t1.x, t1.y, t1.z, t1.w};
#pragma unroll
        for (int ii = 0; ii < 4; ii++)
#pragma unroll
            for (int jj = 0; jj < 8; jj++) acc[ii][jj] += bsv[jj];
    }

    float gv[8], ev[8];
    if (EMODE == 1) {
        const float* gp = gamma + sc * 256;
        const float* bp = beta + sc * 256;
        float4 t0 = *reinterpret_cast<const float4*>(gp + c0);
        float4 t1 = *reinterpret_cast<const float4*>(gp + c1);
        gv[0]=t0.x; gv[1]=t0.y; gv[2]=t0.z; gv[3]=t0.w;
        gv[4]=t1.x; gv[5]=t1.y; gv[6]=t1.z; gv[7]=t1.w;
        float4 u0 = *reinterpret_cast<const float4*>(bp + c0);
        float4 u1 = *reinterpret_cast<const float4*>(bp + c1);
        ev[0]=u0.x; ev[1]=u0.y; ev[2]=u0.z; ev[3]=u0.w;
        ev[4]=u1.x; ev[5]=u1.y; ev[6]=u1.z; ev[7]=u1.w;
    }

#pragma unroll
    for (int ii = 0; ii < 4; ii++) {
        const int row = rowoff + rowblock + warp * 4 + ii;
        float o8[8];
        if (EMODE == 1) {
            float sum = 0.f;
#pragma unroll
            for (int jj = 0; jj < 8; jj++) sum += acc[ii][jj];
#pragma unroll
            for (int o = 16; o > 0; o >>= 1) sum += __shfl_xor_sync(0xFFFFFFFFu, sum, o);
            const float mu = sum * (1.0f / 256.0f);
            float sq = 0.f;
#pragma unroll
            for (int jj = 0; jj < 8; jj++) {
                float dd = acc[ii][jj] - mu;
                sq += dd * dd;
            }
#pragma unroll
            for (int o = 16; o > 0; o >>= 1) sq += __shfl_xor_sync(0xFFFFFFFFu, sq, o);
            const float sc2 = rsqrtf(sq * (1.0f / 256.0f) + 1e-5f);
#pragma unroll
            for (int jj = 0; jj < 8; jj++) {
                float v = fmaf((acc[ii][jj] - mu) * sc2, gv[jj], ev[jj]);
                o8[jj] = fmaxf(v, 0.f);
            }
        } else {
#pragma unroll
            for (int jj = 0; jj < 8; jj++) o8[jj] = acc[ii][jj];
        }
        float4 s0 = make_float4(o8[0], o8[1], o8[2], o8[3]);
        float4 s1 = make_float4(o8[4], o8[5], o8[6], o8[7]);
        if (EMODE == 2) {
            const int bb2 = row >> 11, m = row & 2047;
            const size_t base0 = ((size_t)bb2 * 8192 + m) * 256;
#pragma unroll
            for (int rep = 0; rep < 4; rep++) {
                *reinterpret_cast<float4*>(C + base0 + (size_t)rep * 524288 + c0) = s0;
                *reinterpret_cast<float4*>(C + base0 + (size_t)rep * 524288 + c1) = s1;
            }
        } else {
            *reinterpret_cast<float4*>(C + (size_t)row * 256 + c0) = s0;
            *reinterpret_cast<float4*>(C + (size_t)row * 256 + c1) = s1;
        }
    }
}

// ---------------------------------------------------------------------------
extern "C" void kernel_launch(void* const* d_in, const int* in_sizes, int n_in,
                              void* d_out, int out_size)
{
    const float* features = (const float*)d_in[0];
    const float* xyz      = (const float*)d_in[1];
    const float* w1  = (const float*)d_in[2];
    const float* b1  = (const float*)d_in[3];
    const float* g1  = (const float*)d_in[4];
    const float* be1 = (const float*)d_in[5];
    const float* w2  = (const float*)d_in[6];
    const float* b2  = (const float*)d_in[7];
    const float* fw1 = (const float*)d_in[8];
    const float* fb1 = (const float*)d_in[9];
    const float* fg  = (const float*)d_in[10];
    const float* fbe = (const float*)d_in[11];
    const float* fw2 = (const float*)d_in[12];
    const float* fb2 = (const float*)d_in[13];
    float* out = (float*)d_out;

    int*   idxp;
    float* hp;
    float* procp;
    cudaGetSymbolAddress((void**)&idxp, g_idx);
    cudaGetSymbolAddress((void**)&hp, g_h);
    cudaGetSymbolAddress((void**)&procp, g_proc);

    // 1) One FPS run per batch for the largest scale; smaller scales are prefixes.
    fps_kernel<<<BATCH, 1024>>>(xyz, idxp);

    // 2) All 3 per-scale MLPs, each layer as ONE 896-CTA launch.
    gemm_fused<0, 1><<<896, 256>>>(features, w1, b1, g1, be1, hp, 256, idxp);
    gemm_fused<3, 0><<<896, 256>>>(hp, w2, b2, nullptr, nullptr, procp, 256, nullptr);

    // 3) Fusion MLP on only B*2048 distinct rows (output depends on n mod 2048),
    //    final GEMM epilogue writes each row 4x to rebuild [B, 8192, D].
    gemm_fused<2, 1><<<512, 256>>>(procp, fw1, fb1, fg, fbe, hp, 768, nullptr);
    gemm_fused<1, 2><<<512, 256>>>(hp, fw2, fb2, nullptr, nullptr, out, 256, nullptr);
}